// round 12
// baseline (speedup 1.0000x reference)
#include <cuda_runtime.h>
#include <cuda_bf16.h>
#include <cuda_fp16.h>
#include <cstdint>

// Problem constants
#define NB   64
#define NT   1000
#define NN   512
#define NI   512
#define NM   (NB*NT)

#define ZS_ELEMS   (NB*NT*NN)
#define ST_STRIDE  ((NT+1)*NN)

// ---------------------------------------------------------------------------
// Scratch (device globals — no allocation allowed)
// g_curh layout is (t, b, n): row m = t*NB + b  (time-major production!)
// ---------------------------------------------------------------------------
__device__ __align__(16) __half g_curh[(size_t)NM * NN];
__device__ float  g_Rt[NN * NN];
__device__ __align__(16) __half g_xh[(size_t)NM * NI];
__device__ __align__(16) __half g_wh[NN * NI];
#define NMB 500                       // m-blocks (128 rows each)
__device__ int g_flag[NMB];           // per-m-block completion count (8 n-tiles)

// ---------------------------------------------------------------------------
// Portable PTX helpers (sm_80+ only — tcgen05 unavailable at compute_103)
// ---------------------------------------------------------------------------
__device__ __forceinline__ uint32_t smem_to_u32(const void* p) {
    uint32_t a;
    asm("{ .reg .u64 t; cvta.to.shared.u64 t, %1; cvt.u32.u64 %0, t; }" : "=r"(a) : "l"(p));
    return a;
}
__device__ __forceinline__ void cp_async16(uint32_t dst, const void* src) {
    asm volatile("cp.async.cg.shared.global [%0], [%1], 16;" :: "r"(dst), "l"(src) : "memory");
}
__device__ __forceinline__ void ldsm_x4(uint32_t r[4], uint32_t addr) {
    asm volatile("ldmatrix.sync.aligned.m8n8.x4.shared.b16 {%0,%1,%2,%3}, [%4];"
        : "=r"(r[0]), "=r"(r[1]), "=r"(r[2]), "=r"(r[3]) : "r"(addr));
}
__device__ __forceinline__ void mma16816f(float d[4], const uint32_t a[4], const uint32_t b[2]) {
    asm volatile("mma.sync.aligned.m16n8k16.row.col.f32.f16.f16.f32 "
        "{%0,%1,%2,%3}, {%4,%5,%6,%7}, {%8,%9}, {%0,%1,%2,%3};"
        : "+f"(d[0]), "+f"(d[1]), "+f"(d[2]), "+f"(d[3])
        : "r"(a[0]), "r"(a[1]), "r"(a[2]), "r"(a[3]), "r"(b[0]), "r"(b[1]));
}
#define SWZ(off) ((off) ^ (((off) >> 3) & 0x70))

// ---------------------------------------------------------------------------
// prep_all: transpose R, convert W and x to f16, zero the flags.
// ---------------------------------------------------------------------------
#define TR_BLOCKS 256
#define W_BLOCKS  ((NN * NI / 4) / 256)  // 256
#define X_BLOCKS  ((NM * NI / 4) / 256)  // 32768
__global__ __launch_bounds__(256) void prep_all(const float* __restrict__ R,
                                                const float* __restrict__ W,
                                                const float* __restrict__ x) {
    int blk = blockIdx.x;
    if (blk < TR_BLOCKS) {
        if (blk == 0) {   // zero flags (500 ints)
            for (int i = threadIdx.x; i < NMB; i += 256) g_flag[i] = 0;
        }
        __shared__ float tile[32][33];
        int bx = (blk & 15) * 32, by = (blk >> 4) * 32;
        int tx = threadIdx.x & 31, ty8 = threadIdx.x >> 5;
#pragma unroll
        for (int r = 0; r < 4; r++) {
            int y = ty8 + r * 8;
            tile[y][tx] = R[(by + y) * NN + bx + tx];
        }
        __syncthreads();
#pragma unroll
        for (int r = 0; r < 4; r++) {
            int y = ty8 + r * 8;
            g_Rt[(bx + y) * NN + (by + tx)] = tile[tx][y];
        }
    } else if (blk < TR_BLOCKS + W_BLOCKS) {
        int i = (blk - TR_BLOCKS) * 256 + threadIdx.x;
        float4 v = ((const float4*)W)[i];
        ushort4 o;
        o.x = __half_as_ushort(__float2half_rn(v.x));
        o.y = __half_as_ushort(__float2half_rn(v.y));
        o.z = __half_as_ushort(__float2half_rn(v.z));
        o.w = __half_as_ushort(__float2half_rn(v.w));
        ((ushort4*)g_wh)[i] = o;
    } else {
        int i = (blk - TR_BLOCKS - W_BLOCKS) * 256 + threadIdx.x;
        float4 v = ((const float4*)x)[i];
        ushort4 o;
        o.x = __half_as_ushort(__float2half_rn(v.x));
        o.y = __half_as_ushort(__float2half_rn(v.y));
        o.z = __half_as_ushort(__float2half_rn(v.z));
        o.w = __half_as_ushort(__float2half_rn(v.w));
        ((ushort4*)g_xh)[i] = o;
    }
}

// ---------------------------------------------------------------------------
// Fused kernel: blockIdx 0-127 = scan role (2 CTAs per batch, stream-split),
// blockIdx 128+ = GEMM role (t-major m-blocks, flags published per m-block).
// ---------------------------------------------------------------------------
#define BK       64
#define NCHUNK   (NI / BK)       // 8
#define NSTAGE   3
#define STAGE_B  (192 * 128)     // 24576
#define GEMM_SMEM (NSTAGE * STAGE_B)   // 73728
#define SCAN_CTAS (2 * NB)       // 128
#define CUR_STRIDE (NB * NN / 4) // uint2 elements per t-slice (8192)

__device__ __forceinline__ float4 cvt_cur(uint2 cr) {
    float2 c01 = __half22float2(*(__half2*)&cr.x);
    float2 c23 = __half22float2(*(__half2*)&cr.y);
    float4 c; c.x = c01.x; c.y = c01.y; c.z = c23.x; c.w = c23.y;
    return c;
}

__global__ __launch_bounds__(128, 3) void fused_gemm_scan(
    const float* __restrict__ bias,
    const float* __restrict__ beta,
    const float* __restrict__ beta2,
    const float* __restrict__ decay_v,
    const float* __restrict__ decay_b,
    float* __restrict__ out)
{
    extern __shared__ char smem[];
    const int tid = threadIdx.x, lane = tid & 31, wid = tid >> 5;

    if (blockIdx.x >= SCAN_CTAS) {
        // ================= GEMM role =================
        uint32_t sb = smem_to_u32(smem);
        const int g  = blockIdx.x - SCAN_CTAS;
        const int mb = g >> 3;             // t-major m-block
        const int n0 = (g & 7) * 64;
        const int m0 = mb * 128;
        const int wm = (wid & 1) * 64;
        const int wn = (wid >> 1) * 32;

        float acc[4][4][4];
#pragma unroll
        for (int i = 0; i < 4; i++)
#pragma unroll
            for (int j = 0; j < 4; j++)
#pragma unroll
                for (int k = 0; k < 4; k++) acc[i][j][k] = 0.f;

        // A row for m = t*NB + b  ->  x row = b*NT + t
        const int m = m0 + tid;
        const int xrow = (m & (NB - 1)) * NT + (m >> 6);
        const __half* pA = g_xh + (size_t)xrow * NI;
        const bool hasB = (tid < 64);
        const __half* pB = g_wh + (size_t)(n0 + (tid & 63)) * NI;
        const uint32_t rowA = (uint32_t)tid * 128;
        const uint32_t rowB = (uint32_t)(128 + tid) * 128;

        auto load_chunk = [&](int c) {
            uint32_t base = sb + (uint32_t)(c % NSTAGE) * STAGE_B;
#pragma unroll
            for (int j = 0; j < 8; j++)
                cp_async16(base + SWZ(rowA + j * 16), pA + c * BK + j * 8);
            if (hasB) {
#pragma unroll
                for (int j = 0; j < 8; j++)
                    cp_async16(base + SWZ(rowB + j * 16), pB + c * BK + j * 8);
            }
            asm volatile("cp.async.commit_group;" ::: "memory");
        };

        const int a_row = wm + (lane & 15);
        const int a_cb  = (lane >> 4) * 16;
        const int b_row = 128 + wn + (lane & 7) + ((lane >> 4) * 8);
        const int b_cb  = ((lane >> 3) & 1) * 16;

        load_chunk(0);
        load_chunk(1);

        for (int c = 0; c < NCHUNK; c++) {
            asm volatile("cp.async.wait_group %0;" :: "n"(NSTAGE - 2) : "memory");
            __syncthreads();

            if (c + NSTAGE - 1 < NCHUNK) {
                load_chunk(c + NSTAGE - 1);
            } else {
                asm volatile("cp.async.commit_group;" ::: "memory");
            }

            uint32_t base = sb + (uint32_t)(c % NSTAGE) * STAGE_B;
#pragma unroll
            for (int kk = 0; kk < 4; kk++) {
                uint32_t ah[4][4], bh[4][2];
#pragma unroll
                for (int mt = 0; mt < 4; mt++) {
                    uint32_t off = (uint32_t)((a_row + mt * 16) * 128 + kk * 32 + a_cb);
                    ldsm_x4(ah[mt], base + SWZ(off));
                }
#pragma unroll
                for (int p = 0; p < 2; p++) {
                    uint32_t off = (uint32_t)((b_row + p * 16) * 128 + kk * 32 + b_cb);
                    uint32_t t4[4];
                    ldsm_x4(t4, base + SWZ(off));
                    bh[2 * p][0] = t4[0]; bh[2 * p][1] = t4[1];
                    bh[2 * p + 1][0] = t4[2]; bh[2 * p + 1][1] = t4[3];
                }
#pragma unroll
                for (int mt = 0; mt < 4; mt++)
#pragma unroll
                    for (int nt = 0; nt < 4; nt++)
                        mma16816f(acc[mt][nt], ah[mt], bh[nt]);
            }
        }

        const int erow = m0 + wm + (lane >> 2);
        const int ecol0 = n0 + wn + (lane & 3) * 2;
        float2 brg[4];
#pragma unroll
        for (int nt = 0; nt < 4; nt++)
            brg[nt] = *(const float2*)(bias + ecol0 + nt * 8);
#pragma unroll
        for (int mt = 0; mt < 4; mt++) {
            int r0 = erow + mt * 16;
#pragma unroll
            for (int nt = 0; nt < 4; nt++) {
                __half2 h0 = __floats2half2_rn(acc[mt][nt][0] + brg[nt].x,
                                               acc[mt][nt][1] + brg[nt].y);
                __half2 h1 = __floats2half2_rn(acc[mt][nt][2] + brg[nt].x,
                                               acc[mt][nt][3] + brg[nt].y);
                *(__half2*)(g_curh + (size_t)r0 * NN + ecol0 + nt * 8) = h0;
                *(__half2*)(g_curh + (size_t)(r0 + 8) * NN + ecol0 + nt * 8) = h1;
            }
        }

        // publish: all stores visible, then bump this m-block's flag
        __threadfence();
        __syncthreads();
        if (tid == 0) atomicAdd(&g_flag[mb], 1);
        return;
    }

    // ================= scan role =================
    const int b = blockIdx.x >> 1;
    const int p = blockIdx.x & 1;
    const int w = wid;

    __shared__ int wsum[4];
    __shared__ int act[NN];

    const float4 be = ((const float4*)beta)[tid];
    const float4 b2 = ((const float4*)beta2)[tid];
    const float4 dv = ((const float4*)decay_v)[tid];
    const float4 db = ((const float4*)decay_b)[tid];
    const float4 omdv = {1.f - dv.x, 1.f - dv.y, 1.f - dv.z, 1.f - dv.w};
    const float4 omdb = {1.f - db.x, 1.f - db.y, 1.f - db.z, 1.f - db.w};

    float4 v  = {0.f, 0.f, 0.f, 0.f};
    float4 bb = {0.f, 0.f, 0.f, 0.f};
    float4 zp = {0.f, 0.f, 0.f, 0.f};
    int nact = 0;
    int wm_done = 0;   // watermark: m-blocks [0, wm_done) complete (thread 0 only)

    // cur layout (t, b, n): element (t) at cur2[t * CUR_STRIDE]
    const uint2* cur2 = (const uint2*)g_curh + (size_t)b * (NN / 4) + tid;

    float* zsb = out + (size_t)b * NT * NN;
    float* vf  = out + ZS_ELEMS + (size_t)(0 * NB + b) * ST_STRIDE;
    float* zf  = out + ZS_ELEMS + (size_t)(1 * NB + b) * ST_STRIDE;
    float* bf  = out + ZS_ELEMS + (size_t)(2 * NB + b) * ST_STRIDE;

    const float4 zero4 = {0.f, 0.f, 0.f, 0.f};
    if (p == 0) {
        ((float4*)vf)[tid] = zero4;
    } else {
        ((float4*)zf)[tid] = zero4;
        ((float4*)bf)[tid] = zero4;
    }

    // wait until all m-blocks covering t <= need_t are produced
    auto wait_t = [&](int need_t) {
        int need_mb = (need_t >> 1) + 1;   // m-block mb covers t = 2mb, 2mb+1
        if (tid == 0) {
            while (wm_done < need_mb) {
                while (((volatile int*)g_flag)[wm_done] != 8) __nanosleep(200);
                wm_done++;
            }
            __threadfence();
        }
        __syncthreads();
    };

    wait_t(7);
    uint2 cpre[8];
#pragma unroll
    for (int i = 0; i < 8; i++) cpre[i] = cur2[(size_t)i * CUR_STRIDE];

    auto slow_window = [&](int tb) {
        for (int u = 0; u < 8; u++) {
            const int t = tb + u;
            float4 c = cvt_cur(cur2[(size_t)t * CUR_STRIDE]);

            float4 rec = {0.f, 0.f, 0.f, 0.f};
            for (int k = 0; k < nact; k++) {
                float4 r = ((const float4*)g_Rt)[(size_t)act[k] * 128 + tid];
                rec.x += r.x; rec.y += r.y; rec.z += r.z; rec.w += r.w;
            }

            v.x *= (1.f - zp.x); v.y *= (1.f - zp.y); v.z *= (1.f - zp.z); v.w *= (1.f - zp.w);
            float4 vt;
            vt.x = dv.x * v.x + omdv.x * ((c.x + rec.x) - bb.x);
            vt.y = dv.y * v.y + omdv.y * ((c.y + rec.y) - bb.y);
            vt.z = dv.z * v.z + omdv.z * ((c.z + rec.z) - bb.z);
            vt.w = dv.w * v.w + omdv.w * ((c.w + rec.w) - bb.w);
            float4 zt;
            zt.x = (vt.x >= 1.0f) ? 1.f : 0.f;
            zt.y = (vt.y >= 1.0f) ? 1.f : 0.f;
            zt.z = (vt.z >= 1.0f) ? 1.f : 0.f;
            zt.w = (vt.w >= 1.0f) ? 1.f : 0.f;
            bb.x = db.x * bb.x + omdb.x * (be.x * vt.x + b2.x * zt.x);
            bb.y = db.y * bb.y + omdb.y * (be.y * vt.y + b2.y * zt.y);
            bb.z = db.z * bb.z + omdb.z * (be.z * vt.z + b2.z * zt.z);
            bb.w = db.w * bb.w + omdb.w * (be.w * vt.w + b2.w * zt.w);
            v = vt; zp = zt;

            size_t tpo = (size_t)(t + 1) * 128 + tid;
            if (p == 0) {
                ((float4*)zsb)[(size_t)t * 128 + tid] = zt;
                ((float4*)vf)[tpo] = vt;
            } else {
                ((float4*)zf)[tpo] = zt;
                ((float4*)bf)[tpo] = bb;
            }

            int any = (zt.x != 0.f) | (zt.y != 0.f) | (zt.z != 0.f) | (zt.w != 0.f);
            int flag = __syncthreads_count(any);
            if (flag) {
                int myspk = (zt.x != 0.f) + (zt.y != 0.f) + (zt.z != 0.f) + (zt.w != 0.f);
                int incl = myspk;
#pragma unroll
                for (int d = 1; d < 32; d <<= 1) {
                    int n = __shfl_up_sync(0xffffffffu, incl, d);
                    if (lane >= d) incl += n;
                }
                if (lane == 31) wsum[w] = incl;
                __syncthreads();
                int basep = 0, tot = 0;
#pragma unroll
                for (int i = 0; i < 4; i++) {
                    int sv = wsum[i];
                    if (i < w) basep += sv;
                    tot += sv;
                }
                int pos = basep + incl - myspk;
                int o0 = tid * 4;
                if (zt.x != 0.f) act[pos++] = o0 + 0;
                if (zt.y != 0.f) act[pos++] = o0 + 1;
                if (zt.z != 0.f) act[pos++] = o0 + 2;
                if (zt.w != 0.f) act[pos++] = o0 + 3;
                __syncthreads();
                nact = tot;
            } else {
                nact = 0;
            }
        }
#pragma unroll
        for (int u = 0; u < 8; u++) {
            int tp = tb + 8 + u;
            if (tp < NT) cpre[u] = cur2[(size_t)tp * CUR_STRIDE];
        }
    };

    for (int tb = 0; tb < NT; tb += 8) {
        wait_t(tb + 15 < NT ? tb + 15 : NT - 1);   // covers window + prefetch
        if (nact == 0) {
            const float4 v0 = v, bb0 = bb;
            int spec = 0;
#pragma unroll
            for (int u = 0; u < 8; u++) {
                const int t = tb + u;
                float4 c = cvt_cur(cpre[u]);
                if (t + 8 < NT) cpre[u] = cur2[(size_t)(t + 8) * CUR_STRIDE];

                float4 vt;
                vt.x = dv.x * v.x + omdv.x * (c.x - bb.x);
                vt.y = dv.y * v.y + omdv.y * (c.y - bb.y);
                vt.z = dv.z * v.z + omdv.z * (c.z - bb.z);
                vt.w = dv.w * v.w + omdv.w * (c.w - bb.w);
                float4 zt;
                zt.x = (vt.x >= 1.0f) ? 1.f : 0.f;
                zt.y = (vt.y >= 1.0f) ? 1.f : 0.f;
                zt.z = (vt.z >= 1.0f) ? 1.f : 0.f;
                zt.w = (vt.w >= 1.0f) ? 1.f : 0.f;
                spec |= (zt.x != 0.f) | (zt.y != 0.f) | (zt.z != 0.f) | (zt.w != 0.f);
                bb.x = db.x * bb.x + omdb.x * (be.x * vt.x + b2.x * zt.x);
                bb.y = db.y * bb.y + omdb.y * (be.y * vt.y + b2.y * zt.y);
                bb.z = db.z * bb.z + omdb.z * (be.z * vt.z + b2.z * zt.z);
                bb.w = db.w * bb.w + omdb.w * (be.w * vt.w + b2.w * zt.w);
                v = vt;

                size_t tpo = (size_t)(t + 1) * 128 + tid;
                if (p == 0) {
                    ((float4*)zsb)[(size_t)t * 128 + tid] = zt;
                    ((float4*)vf)[tpo] = vt;
                } else {
                    ((float4*)zf)[tpo] = zt;
                    ((float4*)bf)[tpo] = bb;
                }
            }
            int flag = __syncthreads_count(spec);
            if (flag) {
                v = v0; bb = bb0; zp = zero4; nact = 0;
                slow_window(tb);
            } else {
                zp = zero4; nact = 0;
            }
        } else {
            slow_window(tb);
        }
    }
}

// ---------------------------------------------------------------------------
extern "C" void kernel_launch(void* const* d_in, const int* in_sizes, int n_in,
                              void* d_out, int out_size) {
    const float* x     = (const float*)d_in[0];
    const float* W     = (const float*)d_in[1];
    const float* bias  = (const float*)d_in[2];
    const float* R     = (const float*)d_in[3];
    const float* beta  = (const float*)d_in[4];
    const float* beta2 = (const float*)d_in[5];
    const float* dvp   = (const float*)d_in[6];
    const float* dbp   = (const float*)d_in[7];
    float* out = (float*)d_out;

    cudaFuncSetAttribute(fused_gemm_scan, cudaFuncAttributeMaxDynamicSharedMemorySize, GEMM_SMEM);

    prep_all<<<TR_BLOCKS + W_BLOCKS + X_BLOCKS, 256>>>(R, W, x);

    fused_gemm_scan<<<SCAN_CTAS + NMB * 8, 128, GEMM_SMEM>>>(
        bias, beta, beta2, dvp, dbp, out);
}